// round 15
// baseline (speedup 1.0000x reference)
#include <cuda_runtime.h>
#include <cuda_bf16.h>
#include <cstdint>

// ---------------------------------------------------------------------------
// StackedBidirectionalLSTMEncoder  (B=64, T=256, V=128, E=512, U=512)
// Round 15: k-split scan — Ur fragments register-resident (loaded once),
// warps own k-slices, partial z reduced through smem. Kills the 524KB/step
// of redundant A-fragment LDS that made R12-R14 smem-bound.
//   embW gather + 3-stage mma_gemm (validated) unchanged.
// ---------------------------------------------------------------------------

#define kB 64
#define kT 256
#define kE 512
#define kU 512
#define kG 2048   /* 4U */
#define kF 1024   /* 2U */

// ------------------------------ scratch ------------------------------------
__device__ float g_zx0[33554432];                   // [t*B+b][2048] fwd (layer2)
__device__ float g_zx1[33554432];                   // bwd
__device__ __nv_bfloat16 g_ah[16777216];            // A hi  [16384][1024]
__device__ __nv_bfloat16 g_al[16777216];            // A lo
__device__ __nv_bfloat16 g_bh0[2097152];            // W2f^T hi [2048][1024]
__device__ __nv_bfloat16 g_bl0[2097152];
__device__ __nv_bfloat16 g_bh1[2097152];            // W2b^T hi
__device__ __nv_bfloat16 g_bl1[2097152];
__device__ float g_embw0[262144];                   // emb@W1f+b1f [128][2048]
__device__ float g_embw1[262144];
__device__ __nv_bfloat16 g_hh[2][2][2][kB * kU];    // [layer][dir][par] h hi
__device__ __nv_bfloat16 g_hl[2][2][2][kB * kU];    // h lo
__device__ unsigned int g_bar[4];                   // [layer*2+dir]

// ------------------------------ f32x2 helpers ------------------------------
__device__ __forceinline__ unsigned long long pk2(float lo, float hi) {
    unsigned long long r;
    asm("mov.b64 %0, {%1, %2};" : "=l"(r) : "f"(lo), "f"(hi));
    return r;
}
__device__ __forceinline__ void upk2(unsigned long long v, float& lo, float& hi) {
    asm("mov.b64 {%0, %1}, %2;" : "=f"(lo), "=f"(hi) : "l"(v));
}
__device__ __forceinline__ unsigned long long ffma2(unsigned long long a,
                                                    unsigned long long b,
                                                    unsigned long long c) {
    unsigned long long d;
    asm("fma.rn.f32x2 %0, %1, %2, %3;" : "=l"(d) : "l"(a), "l"(b), "l"(c));
    return d;
}
__device__ __forceinline__ float sigmoidf_(float x) {
    return 1.0f / (1.0f + __expf(-x));
}
__device__ __forceinline__ uint32_t pack_bf16x2(__nv_bfloat16 a, __nv_bfloat16 b) {
    unsigned short ua = *reinterpret_cast<unsigned short*>(&a);
    unsigned short ub = *reinterpret_cast<unsigned short*>(&b);
    return (uint32_t)ua | ((uint32_t)ub << 16);
}

// ------------------------------ cp.async helpers ----------------------------
__device__ __forceinline__ uint32_t smem_u32(const void* p) {
    uint32_t a;
    asm("{ .reg .u64 t; cvta.to.shared.u64 t, %1; cvt.u32.u64 %0, t; }"
        : "=r"(a) : "l"(p));
    return a;
}
__device__ __forceinline__ void cp16(uint32_t d, const void* s) {
    asm volatile("cp.async.cg.shared.global [%0], [%1], 16;" :: "r"(d), "l"(s));
}
__device__ __forceinline__ void cp_commit() { asm volatile("cp.async.commit_group;" ::: "memory"); }
__device__ __forceinline__ void cp_wait1()  { asm volatile("cp.async.wait_group 1;" ::: "memory"); }
__device__ __forceinline__ void cp_wait0()  { asm volatile("cp.async.wait_group 0;" ::: "memory"); }

// release/acquire barrier primitives (gpu scope)
__device__ __forceinline__ void bar_arrive_release(unsigned int* p) {
    asm volatile("red.release.gpu.global.add.u32 [%0], %1;"
                 :: "l"(p), "r"(1u) : "memory");
}
__device__ __forceinline__ unsigned int bar_poll_acquire(unsigned int* p) {
    unsigned int v;
    asm volatile("ld.acquire.gpu.global.u32 %0, [%1];"
                 : "=r"(v) : "l"(p) : "memory");
    return v;
}

// bf16 warp mma: D(16x8,f32) += A(16x16 row) * B(16x8 col)
__device__ __forceinline__ void mma16816(float* c, const uint32_t* a,
                                         const uint32_t* b) {
    asm volatile(
        "mma.sync.aligned.m16n8k16.row.col.f32.bf16.bf16.f32 "
        "{%0,%1,%2,%3}, {%4,%5,%6,%7}, {%8,%9}, {%0,%1,%2,%3};"
        : "+f"(c[0]), "+f"(c[1]), "+f"(c[2]), "+f"(c[3])
        : "r"(a[0]), "r"(a[1]), "r"(a[2]), "r"(a[3]), "r"(b[0]), "r"(b[1]));
}

// ------------------------------ init ----------------------------------------
__global__ void init_kernel() {
    int i = blockIdx.x * blockDim.x + threadIdx.x;
    if (i < 4) g_bar[i] = 0u;
    uint32_t* h0 = (uint32_t*)g_hh;
    uint32_t* h1 = (uint32_t*)g_hl;
    for (int j = i; j < 2 * 2 * 2 * kB * kU / 2; j += gridDim.x * blockDim.x) {
        h0[j] = 0u;
        h1[j] = 0u;
    }
}

// ------------------------------ fp32 GEMM (embW only; M=128) ---------------
__global__ __launch_bounds__(256, 2) void gemm_f32(
    const float* __restrict__ A, const float* __restrict__ W,
    const float* __restrict__ bias, int c_sel, int K) {
    float* __restrict__ C = c_sel ? g_embw1 : g_embw0;
    __shared__ float As[16][136];
    __shared__ float Bs[16][128];
    const int tid = threadIdx.x;
    const int tx = tid & 15;
    const int ty = tid >> 4;
    const int m0 = blockIdx.y * 128;
    const int n0 = blockIdx.x * 128;

    unsigned long long acc[8][4];
#pragma unroll
    for (int i = 0; i < 8; i++)
#pragma unroll
        for (int j = 0; j < 4; j++) acc[i][j] = pk2(0.0f, 0.0f);

    for (int k0 = 0; k0 < K; k0 += 16) {
#pragma unroll
        for (int l = 0; l < 2; ++l) {
            int f = tid + l * 256;
            int m = f >> 2, kc = (f & 3) * 4;
            float4 v = *(const float4*)(A + (size_t)(m0 + m) * K + k0 + kc);
            As[kc + 0][m] = v.x; As[kc + 1][m] = v.y;
            As[kc + 2][m] = v.z; As[kc + 3][m] = v.w;
            int kr = f >> 5, nc = (f & 31) * 4;
            *(float4*)&Bs[kr][nc] =
                *(const float4*)(W + (size_t)(k0 + kr) * kG + n0 + nc);
        }
        __syncthreads();
#pragma unroll
        for (int k = 0; k < 16; ++k) {
            float4 a0 = *(const float4*)&As[k][ty * 8];
            float4 a1 = *(const float4*)&As[k][ty * 8 + 4];
            float4 b0 = *(const float4*)&Bs[k][tx * 8];
            float4 b1 = *(const float4*)&Bs[k][tx * 8 + 4];
            unsigned long long bp[4] = {pk2(b0.x, b0.y), pk2(b0.z, b0.w),
                                        pk2(b1.x, b1.y), pk2(b1.z, b1.w)};
            float av[8] = {a0.x, a0.y, a0.z, a0.w, a1.x, a1.y, a1.z, a1.w};
#pragma unroll
            for (int i = 0; i < 8; i++) {
                unsigned long long ad = pk2(av[i], av[i]);
#pragma unroll
                for (int j = 0; j < 4; j++) acc[i][j] = ffma2(ad, bp[j], acc[i][j]);
            }
        }
        __syncthreads();
    }
#pragma unroll
    for (int i = 0; i < 8; i++) {
        int m = m0 + ty * 8 + i;
#pragma unroll
        for (int jh = 0; jh < 2; jh++) {
            float l0, h0, l1, h1;
            upk2(acc[i][jh * 2 + 0], l0, h0);
            upk2(acc[i][jh * 2 + 1], l1, h1);
            int n = n0 + tx * 8 + jh * 4;
            float4 v;
            v.x = l0 + bias[n + 0];
            v.y = h0 + bias[n + 1];
            v.z = l1 + bias[n + 2];
            v.w = h1 + bias[n + 3];
            *(float4*)(C + (size_t)m * kG + n) = v;
        }
    }
}

// ------------------------------ W2 transpose + bf16 split -------------------
__global__ void wsplit_kernel(const float* __restrict__ W2f,
                              const float* __restrict__ W2b) {
    __shared__ float s[32][33];
    const int d = blockIdx.z;
    const float* __restrict__ W = d ? W2b : W2f;
    __nv_bfloat16* __restrict__ Bh = d ? g_bh1 : g_bh0;
    __nv_bfloat16* __restrict__ Bl = d ? g_bl1 : g_bl0;
    const int n0 = blockIdx.x * 32, k0 = blockIdx.y * 32;
    const int tx = threadIdx.x & 31, ty = threadIdx.x >> 5;
#pragma unroll
    for (int i = 0; i < 4; ++i) {
        int k = ty + i * 8;
        s[k][tx] = W[(size_t)(k0 + k) * kG + n0 + tx];
    }
    __syncthreads();
#pragma unroll
    for (int i = 0; i < 4; ++i) {
        int r = ty + i * 8;
        float v = s[tx][r];
        __nv_bfloat16 hi = __float2bfloat16(v);
        float lo = v - __bfloat162float(hi);
        size_t o = (size_t)(n0 + r) * 1024 + k0 + tx;
        Bh[o] = hi;
        Bl[o] = __float2bfloat16(lo);
    }
}

// ------------------------------ warp-mma layer-2 GEMM (validated 3-stage) ---
#define TILE_B   10240
#define STAGE_B  (4 * TILE_B)
#define MM_SMEM  (3 * STAGE_B)

__global__ __launch_bounds__(256, 1) void mma_gemm_kernel(
    const float* __restrict__ bias_f, const float* __restrict__ bias_b) {
    extern __shared__ char dynsmem[];
    const int tid = threadIdx.x;
    const int wid = tid >> 5, lane = tid & 31;
    const int g = lane >> 2, t = lane & 3;
    const int wm = wid & 3, wn = wid >> 2;
    const int d = blockIdx.z;
    const int n0 = blockIdx.x * 128;
    const int m0 = blockIdx.y * 128;
    const __nv_bfloat16* __restrict__ Bh = d ? g_bh1 : g_bh0;
    const __nv_bfloat16* __restrict__ Bl = d ? g_bl1 : g_bl0;
    const float* __restrict__ bias = d ? bias_b : bias_f;
    float* __restrict__ zx = d ? g_zx1 : g_zx0;

    const uint32_t sb32 = smem_u32(dynsmem);

    float acc[2][8][4];
#pragma unroll
    for (int mi = 0; mi < 2; mi++)
#pragma unroll
        for (int ni = 0; ni < 8; ni++)
#pragma unroll
            for (int v = 0; v < 4; v++) acc[mi][ni][v] = 0.0f;

    auto load_chunk = [&](int s, int kc) {
        const uint32_t base = sb32 + (uint32_t)s * STAGE_B;
        const int k0 = kc * 32;
        for (int idx = tid; idx < 2048; idx += 256) {
            int tile = idx >> 9;
            int r = (idx >> 2) & 127;
            int c = idx & 3;
            const __nv_bfloat16* src;
            if (tile < 2) src = (tile == 0 ? g_ah : g_al) + (size_t)(m0 + r) * 1024 + k0 + c * 8;
            else          src = (tile == 2 ? Bh : Bl)     + (size_t)(n0 + r) * 1024 + k0 + c * 8;
            cp16(base + tile * TILE_B + r * 80 + c * 16, src);
        }
        cp_commit();
    };

    load_chunk(0, 0);
    load_chunk(1, 1);

    for (int c = 0; c < 32; ++c) {
        if (c + 1 < 32) cp_wait1(); else cp_wait0();
        __syncthreads();
        if (c + 2 < 32) load_chunk((c + 2) % 3, c + 2);

        const char* stg = dynsmem + (size_t)(c % 3) * STAGE_B;
        const char* pAh = stg;
        const char* pAl = stg + TILE_B;
        const char* pBh = stg + 2 * TILE_B;
        const char* pBl = stg + 3 * TILE_B;

#pragma unroll
        for (int ks = 0; ks < 2; ++ks) {
            const int kb = ks * 16;
            uint32_t ah[2][4], al[2][4];
#pragma unroll
            for (int mi = 0; mi < 2; mi++) {
                int ra = wm * 32 + mi * 16 + g;
                int co = (kb + t * 2) * 2;
                ah[mi][0] = *(const uint32_t*)(pAh + (ra)     * 80 + co);
                ah[mi][1] = *(const uint32_t*)(pAh + (ra + 8) * 80 + co);
                ah[mi][2] = *(const uint32_t*)(pAh + (ra)     * 80 + co + 16);
                ah[mi][3] = *(const uint32_t*)(pAh + (ra + 8) * 80 + co + 16);
                al[mi][0] = *(const uint32_t*)(pAl + (ra)     * 80 + co);
                al[mi][1] = *(const uint32_t*)(pAl + (ra + 8) * 80 + co);
                al[mi][2] = *(const uint32_t*)(pAl + (ra)     * 80 + co + 16);
                al[mi][3] = *(const uint32_t*)(pAl + (ra + 8) * 80 + co + 16);
            }
#pragma unroll
            for (int ni = 0; ni < 8; ni++) {
                int rb = wn * 64 + ni * 8 + g;
                int co = (kb + t * 2) * 2;
                uint32_t bh[2], bl[2];
                bh[0] = *(const uint32_t*)(pBh + rb * 80 + co);
                bh[1] = *(const uint32_t*)(pBh + rb * 80 + co + 16);
                bl[0] = *(const uint32_t*)(pBl + rb * 80 + co);
                bl[1] = *(const uint32_t*)(pBl + rb * 80 + co + 16);
#pragma unroll
                for (int mi = 0; mi < 2; mi++) {
                    mma16816(acc[mi][ni], ah[mi], bh);
                    mma16816(acc[mi][ni], al[mi], bh);
                    mma16816(acc[mi][ni], ah[mi], bl);
                }
            }
        }
        __syncthreads();
    }

#pragma unroll
    for (int mi = 0; mi < 2; mi++) {
        int m = m0 + wm * 32 + mi * 16 + g;
#pragma unroll
        for (int ni = 0; ni < 8; ni++) {
            int n = n0 + wn * 64 + ni * 8 + t * 2;
            float bx = __ldg(bias + n), by = __ldg(bias + n + 1);
            float2 v0 = {acc[mi][ni][0] + bx, acc[mi][ni][1] + by};
            float2 v1 = {acc[mi][ni][2] + bx, acc[mi][ni][3] + by};
            *(float2*)(zx + (size_t)m * kG + n) = v0;
            *(float2*)(zx + (size_t)(m + 8) * kG + n) = v1;
        }
    }
}

// ------------------------------ k-split HMMA scan ---------------------------
// 128 CTAs: CTA = dir*64 + g owns 8 units (32 gate rows of z^T).
// Warp w owns k in [64w, 64w+64); Ur fragments (hi+lo) in REGISTERS.
// Partial z^T[32,64] per warp -> smem reduction -> epilogue threads.
#define SC_BSTRIDE 1040
#define SC_PLANE   (64 * SC_BSTRIDE)      /* 66560 */
#define SC_OFF_BL  SC_PLANE
#define SC_OFF_ZR  (2 * SC_PLANE)         /* 133120 */
#define ZR_WSTRIDE 2112                   /* floats: 32 rows x 66 */
#define SCAN_SMEM  (2 * SC_PLANE + 8 * ZR_WSTRIDE * 4)  /* 200704 */

__global__ __launch_bounds__(256, 1) void scan_kernel(
    const float* __restrict__ Ur_f, const float* __restrict__ Ur_b,
    const int* __restrict__ enc,
    float* __restrict__ out2, float* __restrict__ h_final,
    float* __restrict__ c_final, int layer2) {
    extern __shared__ char dynsmem[];
    char* pBh = dynsmem;
    char* pBl = dynsmem + SC_OFF_BL;
    float* zred = (float*)(dynsmem + SC_OFF_ZR);

    const int cta = blockIdx.x;
    const int d = cta >> 6;
    const int g = cta & 63;
    const int j0 = g * 8;
    const int tid = threadIdx.x;
    const int wid = tid >> 5, lane = tid & 31;
    const int fg = lane >> 2, ft = lane & 3;
    const int er = tid >> 2;                 // epilogue batch row 0..63
    const int eu = tid & 3;                  // epilogue units eu, eu+4
    const int spl = tid >> 7;                // staging plane
    const int srow = (tid >> 1) & 63;
    const int shalf = tid & 1;

    const float* __restrict__ Ur = d ? Ur_b : Ur_f;
    const float* __restrict__ ew = d ? g_embw1 : g_embw0;
    const float* __restrict__ zx = d ? g_zx1 : g_zx0;
    unsigned int* barp = &g_bar[layer2 * 2 + d];

    // -------- Ur fragments -> REGISTERS (hi/lo), once -----------------------
    // frag reg r: m += (r&1)*8, k += (r>>1)*8 ; each reg packs (kk, kk+1)
    uint32_t ahr[2][4][4], alr[2][4][4];
#pragma unroll
    for (int mi = 0; mi < 2; ++mi)
#pragma unroll
        for (int ksl = 0; ksl < 4; ++ksl)
#pragma unroll
            for (int r = 0; r < 4; ++r) {
                int m = mi * 16 + fg + ((r & 1) << 3);
                int kk = (wid * 4 + ksl) * 16 + ft * 2 + ((r >> 1) << 3);
                int col = (m >> 3) * kU + j0 + (m & 7);
                float v0 = __ldg(Ur + (size_t)kk * kG + col);
                float v1 = __ldg(Ur + (size_t)(kk + 1) * kG + col);
                __nv_bfloat16 h0 = __float2bfloat16(v0);
                __nv_bfloat16 h1 = __float2bfloat16(v1);
                ahr[mi][ksl][r] = pack_bf16x2(h0, h1);
                __nv_bfloat16 l0 = __float2bfloat16(v0 - __bfloat162float(h0));
                __nv_bfloat16 l1 = __float2bfloat16(v1 - __bfloat162float(h1));
                alr[mi][ksl][r] = pack_bf16x2(l0, l1);
            }

    const uint32_t sdst = smem_u32(dynsmem) +
        (spl ? SC_OFF_BL : 0) + srow * SC_BSTRIDE + shalf * 512;

    float hp[2] = {0.f, 0.f}, cp[2] = {0.f, 0.f};

    for (int s = 0; s < kT; ++s) {
        const int t = d ? (kT - 1 - s) : s;
        const int par = s & 1;
        const __nv_bfloat16* __restrict__ ihh = g_hh[layer2][d][par];
        const __nv_bfloat16* __restrict__ ihl = g_hl[layer2][d][par];
        __nv_bfloat16* __restrict__ ohh = g_hh[layer2][d][par ^ 1];
        __nv_bfloat16* __restrict__ ohl = g_hl[layer2][d][par ^ 1];

        // ---- stage B (h planes), single cp.async group ---------------------
        const __nv_bfloat16* ssrc = (spl ? ihl : ihh) + srow * kU + shalf * 256;
#pragma unroll
        for (int c = 0; c < 32; ++c) cp16(sdst + c * 16, ssrc + c * 8);
        cp_commit();

        // ---- zx / token prefetch -------------------------------------------
        const int tok = __ldg(enc + er * kT + t);
        const int msk = tok != 0;
        float zr[2][4];
        if (!layer2) {
#pragma unroll
            for (int q = 0; q < 4; q++) {
                zr[0][q] = __ldg(ew + (size_t)tok * kG + q * kU + j0 + eu);
                zr[1][q] = __ldg(ew + (size_t)tok * kG + q * kU + j0 + eu + 4);
            }
        } else {
            const float* zb = zx + ((size_t)t * kB + er) * kG;
#pragma unroll
            for (int q = 0; q < 4; q++) {
                zr[0][q] = __ldg(zb + q * kU + j0 + eu);
                zr[1][q] = __ldg(zb + q * kU + j0 + eu + 4);
            }
        }

        cp_wait0();
        __syncthreads();

        // ---- HMMA: warp k-slice, A in regs, ni-outer ------------------------
#pragma unroll
        for (int ni = 0; ni < 8; ++ni) {
            float acc[2][4] = {{0.f, 0.f, 0.f, 0.f}, {0.f, 0.f, 0.f, 0.f}};
            const char* brh = pBh + (ni * 8 + fg) * SC_BSTRIDE;
            const char* brl = pBl + (ni * 8 + fg) * SC_BSTRIDE;
#pragma unroll
            for (int ksl = 0; ksl < 4; ++ksl) {
                const int co = ((wid * 4 + ksl) * 16 + ft * 2) * 2;
                uint32_t bh[2], bl[2];
                bh[0] = *(const uint32_t*)(brh + co);
                bh[1] = *(const uint32_t*)(brh + co + 16);
                bl[0] = *(const uint32_t*)(brl + co);
                bl[1] = *(const uint32_t*)(brl + co + 16);
#pragma unroll
                for (int mi = 0; mi < 2; ++mi) {
                    mma16816(acc[mi], ahr[mi][ksl], bh);
                    mma16816(acc[mi], alr[mi][ksl], bh);
                    mma16816(acc[mi], ahr[mi][ksl], bl);
                }
            }
            // partial z store
#pragma unroll
            for (int mi = 0; mi < 2; ++mi)
#pragma unroll
                for (int j = 0; j < 2; ++j) {
                    int m = mi * 16 + fg + j * 8;
                    float2 v = {acc[mi][j * 2], acc[mi][j * 2 + 1]};
                    *(float2*)&zred[wid * ZR_WSTRIDE + m * 66 + ni * 8 + ft * 2] = v;
                }
        }
        __syncthreads();

        // ---- reduction + LSTM epilogue: thread owns (er,eu),(er,eu+4) -------
        float hn_s[2], cn_s[2];
        __nv_bfloat16 bhi_s[2], blo_s[2];
#pragma unroll
        for (int uu = 0; uu < 2; ++uu) {
            const int u = eu + uu * 4;
            float zs[4];
#pragma unroll
            for (int q = 0; q < 4; ++q) {
                const int m = q * 8 + u;
                float sum = 0.f;
#pragma unroll
                for (int w = 0; w < 8; ++w)
                    sum += zred[w * ZR_WSTRIDE + m * 66 + er];
                zs[q] = sum;
            }
            float zi = zs[0] + zr[uu][0];
            float zf = zs[1] + zr[uu][1];
            float zg = zs[2] + zr[uu][2];
            float zo = zs[3] + zr[uu][3];
            float ii = sigmoidf_(zi), ff = sigmoidf_(zf);
            float gg = tanhf(zg), oo = sigmoidf_(zo);
            float cn = ff * cp[uu] + ii * gg;
            float hn = oo * tanhf(cn);
            if (!msk) { hn = hp[uu]; cn = cp[uu]; }
            hp[uu] = hn; cp[uu] = cn;
            hn_s[uu] = hn; cn_s[uu] = cn;
            __nv_bfloat16 bhi = __float2bfloat16(hn);
            __nv_bfloat16 blo = __float2bfloat16(hn - __bfloat162float(bhi));
            bhi_s[uu] = bhi; blo_s[uu] = blo;
            ohh[er * kU + j0 + u] = bhi;
            ohl[er * kU + j0 + u] = blo;
        }

        if (s != kT - 1) {
            __syncthreads();
            if (tid == 0) bar_arrive_release(barp);
#pragma unroll
            for (int uu = 0; uu < 2; ++uu) {
                const int u = eu + uu * 4;
                if (!layer2) {
                    size_t idx = ((size_t)t * kB + er) * kF + d * kU + j0 + u;
                    g_ah[idx] = bhi_s[uu];
                    g_al[idx] = blo_s[uu];
                } else {
                    out2[((size_t)er * kT + t) * kF + d * kU + j0 + u] = hn_s[uu];
                }
            }
            if (tid == 0) {
                unsigned tgt = 64u * (unsigned)(s + 1);
                while (bar_poll_acquire(barp) < tgt) { }
            }
            __syncthreads();
        } else {
#pragma unroll
            for (int uu = 0; uu < 2; ++uu) {
                const int u = eu + uu * 4;
                if (!layer2) {
                    size_t idx = ((size_t)t * kB + er) * kF + d * kU + j0 + u;
                    g_ah[idx] = bhi_s[uu];
                    g_al[idx] = blo_s[uu];
                } else {
                    out2[((size_t)er * kT + t) * kF + d * kU + j0 + u] = hn_s[uu];
                    h_final[er * kF + d * kU + j0 + u] = hn_s[uu];
                    c_final[er * kF + d * kU + j0 + u] = cn_s[uu];
                }
            }
        }
    }
}

// ------------------------------ launch --------------------------------------
extern "C" void kernel_launch(void* const* d_in, const int* in_sizes, int n_in,
                              void* d_out, int out_size) {
    const int*   enc = (const int*)d_in[0];
    const float* emb = (const float*)d_in[1];
    const float* W1f = (const float*)d_in[2];
    const float* U1f = (const float*)d_in[3];
    const float* b1f = (const float*)d_in[4];
    const float* W1b = (const float*)d_in[5];
    const float* U1b = (const float*)d_in[6];
    const float* b1b = (const float*)d_in[7];
    const float* W2f = (const float*)d_in[8];
    const float* U2f = (const float*)d_in[9];
    const float* b2f = (const float*)d_in[10];
    const float* W2b = (const float*)d_in[11];
    const float* U2b = (const float*)d_in[12];
    const float* b2b = (const float*)d_in[13];

    float* out  = (float*)d_out;
    float* out2 = out;                                   // [B,T,2U]
    float* h2   = out + (size_t)kB * kT * kF;
    float* c2   = h2 + (size_t)kB * kF;

    cudaFuncSetAttribute(scan_kernel, cudaFuncAttributeMaxDynamicSharedMemorySize,
                         SCAN_SMEM);
    cudaFuncSetAttribute(mma_gemm_kernel, cudaFuncAttributeMaxDynamicSharedMemorySize,
                         MM_SMEM);

    // embW = emb @ W1 + b1  (V=128 -> gather replaces layer-1 GEMM)
    gemm_f32<<<dim3(16, 1), 256>>>(emb, W1f, b1f, 0, kE);
    gemm_f32<<<dim3(16, 1), 256>>>(emb, W1b, b1b, 1, kE);

    // W2 transpose + bf16 hi/lo split
    wsplit_kernel<<<dim3(64, 32, 2), 256>>>(W2f, W2b);

    // zero h planes + barrier counters
    init_kernel<<<128, 256>>>();

    // layer-1 scan (k-split HMMA; emits bf16 hi/lo A operand)
    scan_kernel<<<128, 256, SCAN_SMEM>>>(U1f, U1b, enc,
                                         nullptr, nullptr, nullptr, 0);

    // layer-2 input projection: warp-mma bf16, 3-pass split, 3-stage pipeline
    mma_gemm_kernel<<<dim3(16, 128, 2), 256, MM_SMEM>>>(b2f, b2b);

    // layer-2 scan -> outputs
    scan_kernel<<<128, 256, SCAN_SMEM>>>(U2f, U2b, enc,
                                         out2, h2, c2, 1);
}

// round 16
// speedup vs baseline: 1.1784x; 1.1784x over previous
#include <cuda_runtime.h>
#include <cuda_bf16.h>
#include <cstdint>

// ---------------------------------------------------------------------------
// StackedBidirectionalLSTMEncoder  (B=64, T=256, V=128, E=512, U=512)
// Round 16: R12 scan (best measured) + R14 barrier (release/acquire spin,
// deferred output stores) + fused BM=32 embW GEMM. Nothing else changed.
// ---------------------------------------------------------------------------

#define kB 64
#define kT 256
#define kE 512
#define kU 512
#define kG 2048   /* 4U */
#define kF 1024   /* 2U */

// ------------------------------ scratch ------------------------------------
__device__ float g_zx0[33554432];                   // [t*B+b][2048] fwd (layer2)
__device__ float g_zx1[33554432];                   // bwd
__device__ __nv_bfloat16 g_ah[16777216];            // A hi  [16384][1024]
__device__ __nv_bfloat16 g_al[16777216];            // A lo
__device__ __nv_bfloat16 g_bh0[2097152];            // W2f^T hi [2048][1024]
__device__ __nv_bfloat16 g_bl0[2097152];
__device__ __nv_bfloat16 g_bh1[2097152];            // W2b^T hi
__device__ __nv_bfloat16 g_bl1[2097152];
__device__ float g_embw0[262144];                   // emb@W1f+b1f [128][2048]
__device__ float g_embw1[262144];
__device__ uint32_t g_hc[2][2][2][kB * kU];         // [layer][dir][par] hi|lo<<16
__device__ unsigned int g_bar[4];                   // [layer*2+dir]

// ------------------------------ f32x2 helpers ------------------------------
__device__ __forceinline__ unsigned long long pk2(float lo, float hi) {
    unsigned long long r;
    asm("mov.b64 %0, {%1, %2};" : "=l"(r) : "f"(lo), "f"(hi));
    return r;
}
__device__ __forceinline__ void upk2(unsigned long long v, float& lo, float& hi) {
    asm("mov.b64 {%0, %1}, %2;" : "=f"(lo), "=f"(hi) : "l"(v));
}
__device__ __forceinline__ unsigned long long ffma2(unsigned long long a,
                                                    unsigned long long b,
                                                    unsigned long long c) {
    unsigned long long d;
    asm("fma.rn.f32x2 %0, %1, %2, %3;" : "=l"(d) : "l"(a), "l"(b), "l"(c));
    return d;
}
__device__ __forceinline__ float sigmoidf_(float x) {
    return 1.0f / (1.0f + __expf(-x));
}

// ------------------------------ cp.async helpers ----------------------------
__device__ __forceinline__ uint32_t smem_u32(const void* p) {
    uint32_t a;
    asm("{ .reg .u64 t; cvta.to.shared.u64 t, %1; cvt.u32.u64 %0, t; }"
        : "=r"(a) : "l"(p));
    return a;
}
__device__ __forceinline__ void cp16(uint32_t d, const void* s) {
    asm volatile("cp.async.cg.shared.global [%0], [%1], 16;" :: "r"(d), "l"(s));
}
__device__ __forceinline__ void cp_commit() { asm volatile("cp.async.commit_group;" ::: "memory"); }
__device__ __forceinline__ void cp_wait1()  { asm volatile("cp.async.wait_group 1;" ::: "memory"); }
__device__ __forceinline__ void cp_wait0()  { asm volatile("cp.async.wait_group 0;" ::: "memory"); }

// release/acquire barrier primitives (gpu scope)
__device__ __forceinline__ void bar_arrive_release(unsigned int* p) {
    asm volatile("red.release.gpu.global.add.u32 [%0], %1;"
                 :: "l"(p), "r"(1u) : "memory");
}
__device__ __forceinline__ unsigned int bar_poll_acquire(unsigned int* p) {
    unsigned int v;
    asm volatile("ld.acquire.gpu.global.u32 %0, [%1];"
                 : "=r"(v) : "l"(p) : "memory");
    return v;
}

// bf16 warp mma: D(16x8,f32) += A(16x16 row) * B(16x8 col)
__device__ __forceinline__ void mma16816(float* c, const uint32_t* a,
                                         const uint32_t* b) {
    asm volatile(
        "mma.sync.aligned.m16n8k16.row.col.f32.bf16.bf16.f32 "
        "{%0,%1,%2,%3}, {%4,%5,%6,%7}, {%8,%9}, {%0,%1,%2,%3};"
        : "+f"(c[0]), "+f"(c[1]), "+f"(c[2]), "+f"(c[3])
        : "r"(a[0]), "r"(a[1]), "r"(a[2]), "r"(a[3]), "r"(b[0]), "r"(b[1]));
}

// ------------------------------ init ----------------------------------------
__global__ void init_kernel() {
    int i = blockIdx.x * blockDim.x + threadIdx.x;
    if (i < 4) g_bar[i] = 0u;
    uint32_t* h = (uint32_t*)g_hc;
    for (int j = i; j < 2 * 2 * 2 * kB * kU; j += gridDim.x * blockDim.x) h[j] = 0u;
}

// ------------------------------ fp32 GEMM (embW; BM=32, fused f/b) ---------
// C selected IN DEVICE CODE — never pass __device__ symbols from host.
__global__ __launch_bounds__(256, 2) void gemm_f32(
    const float* __restrict__ A,
    const float* __restrict__ Wf, const float* __restrict__ biasf,
    const float* __restrict__ Wb, const float* __restrict__ biasb) {
    const int zsel = blockIdx.z;
    const float* __restrict__ W = zsel ? Wb : Wf;
    const float* __restrict__ bias = zsel ? biasb : biasf;
    float* __restrict__ C = zsel ? g_embw1 : g_embw0;
    __shared__ float As[16][36];
    __shared__ float Bs[16][128];
    const int tid = threadIdx.x;
    const int tx = tid & 31;
    const int ty = tid >> 5;
    const int m0 = blockIdx.y * 32;
    const int n0 = blockIdx.x * 128;

    unsigned long long acc[4][2];
#pragma unroll
    for (int i = 0; i < 4; i++) { acc[i][0] = pk2(0.f, 0.f); acc[i][1] = pk2(0.f, 0.f); }

    for (int k0 = 0; k0 < kE; k0 += 16) {
        if (tid < 128) {
            int m = tid >> 2, kc = (tid & 3) * 4;
            float4 v = *(const float4*)(A + (size_t)(m0 + m) * kE + k0 + kc);
            As[kc + 0][m] = v.x; As[kc + 1][m] = v.y;
            As[kc + 2][m] = v.z; As[kc + 3][m] = v.w;
        }
#pragma unroll
        for (int l = 0; l < 2; ++l) {
            int f = tid + l * 256;
            int kr = f >> 5, nc = (f & 31) * 4;
            *(float4*)&Bs[kr][nc] =
                *(const float4*)(W + (size_t)(k0 + kr) * kG + n0 + nc);
        }
        __syncthreads();
#pragma unroll
        for (int k = 0; k < 16; ++k) {
            float4 a = *(const float4*)&As[k][ty * 4];
            float4 b = *(const float4*)&Bs[k][tx * 4];
            unsigned long long bp0 = pk2(b.x, b.y), bp1 = pk2(b.z, b.w);
            float av[4] = {a.x, a.y, a.z, a.w};
#pragma unroll
            for (int i = 0; i < 4; ++i) {
                unsigned long long ad = pk2(av[i], av[i]);
                acc[i][0] = ffma2(ad, bp0, acc[i][0]);
                acc[i][1] = ffma2(ad, bp1, acc[i][1]);
            }
        }
        __syncthreads();
    }
#pragma unroll
    for (int i = 0; i < 4; ++i) {
        int m = m0 + ty * 4 + i;
        int n = n0 + tx * 4;
        float l0, h0, l1, h1;
        upk2(acc[i][0], l0, h0);
        upk2(acc[i][1], l1, h1);
        float4 v;
        v.x = l0 + bias[n + 0];
        v.y = h0 + bias[n + 1];
        v.z = l1 + bias[n + 2];
        v.w = h1 + bias[n + 3];
        *(float4*)(C + (size_t)m * kG + n) = v;
    }
}

// ------------------------------ W2 transpose + bf16 split -------------------
__global__ void wsplit_kernel(const float* __restrict__ W2f,
                              const float* __restrict__ W2b) {
    __shared__ float s[32][33];
    const int d = blockIdx.z;
    const float* __restrict__ W = d ? W2b : W2f;
    __nv_bfloat16* __restrict__ Bh = d ? g_bh1 : g_bh0;
    __nv_bfloat16* __restrict__ Bl = d ? g_bl1 : g_bl0;
    const int n0 = blockIdx.x * 32, k0 = blockIdx.y * 32;
    const int tx = threadIdx.x & 31, ty = threadIdx.x >> 5;
#pragma unroll
    for (int i = 0; i < 4; ++i) {
        int k = ty + i * 8;
        s[k][tx] = W[(size_t)(k0 + k) * kG + n0 + tx];
    }
    __syncthreads();
#pragma unroll
    for (int i = 0; i < 4; ++i) {
        int r = ty + i * 8;
        float v = s[tx][r];
        __nv_bfloat16 hi = __float2bfloat16(v);
        float lo = v - __bfloat162float(hi);
        size_t o = (size_t)(n0 + r) * 1024 + k0 + tx;
        Bh[o] = hi;
        Bl[o] = __float2bfloat16(lo);
    }
}

// ------------------------------ warp-mma layer-2 GEMM (validated 3-stage) ---
#define TILE_B   10240
#define STAGE_B  (4 * TILE_B)
#define MM_SMEM  (3 * STAGE_B)

__global__ __launch_bounds__(256, 1) void mma_gemm_kernel(
    const float* __restrict__ bias_f, const float* __restrict__ bias_b) {
    extern __shared__ char dynsmem[];
    const int tid = threadIdx.x;
    const int wid = tid >> 5, lane = tid & 31;
    const int g = lane >> 2, t = lane & 3;
    const int wm = wid & 3, wn = wid >> 2;
    const int d = blockIdx.z;
    const int n0 = blockIdx.x * 128;
    const int m0 = blockIdx.y * 128;
    const __nv_bfloat16* __restrict__ Bh = d ? g_bh1 : g_bh0;
    const __nv_bfloat16* __restrict__ Bl = d ? g_bl1 : g_bl0;
    const float* __restrict__ bias = d ? bias_b : bias_f;
    float* __restrict__ zx = d ? g_zx1 : g_zx0;

    const uint32_t sb32 = smem_u32(dynsmem);

    float acc[2][8][4];
#pragma unroll
    for (int mi = 0; mi < 2; mi++)
#pragma unroll
        for (int ni = 0; ni < 8; ni++)
#pragma unroll
            for (int v = 0; v < 4; v++) acc[mi][ni][v] = 0.0f;

    auto load_chunk = [&](int s, int kc) {
        const uint32_t base = sb32 + (uint32_t)s * STAGE_B;
        const int k0 = kc * 32;
        for (int idx = tid; idx < 2048; idx += 256) {
            int tile = idx >> 9;
            int r = (idx >> 2) & 127;
            int c = idx & 3;
            const __nv_bfloat16* src;
            if (tile < 2) src = (tile == 0 ? g_ah : g_al) + (size_t)(m0 + r) * 1024 + k0 + c * 8;
            else          src = (tile == 2 ? Bh : Bl)     + (size_t)(n0 + r) * 1024 + k0 + c * 8;
            cp16(base + tile * TILE_B + r * 80 + c * 16, src);
        }
        cp_commit();
    };

    load_chunk(0, 0);
    load_chunk(1, 1);

    for (int c = 0; c < 32; ++c) {
        if (c + 1 < 32) cp_wait1(); else cp_wait0();
        __syncthreads();
        if (c + 2 < 32) load_chunk((c + 2) % 3, c + 2);

        const char* stg = dynsmem + (size_t)(c % 3) * STAGE_B;
        const char* pAh = stg;
        const char* pAl = stg + TILE_B;
        const char* pBh = stg + 2 * TILE_B;
        const char* pBl = stg + 3 * TILE_B;

#pragma unroll
        for (int ks = 0; ks < 2; ++ks) {
            const int kb = ks * 16;
            uint32_t ah[2][4], al[2][4];
#pragma unroll
            for (int mi = 0; mi < 2; mi++) {
                int ra = wm * 32 + mi * 16 + g;
                int co = (kb + t * 2) * 2;
                ah[mi][0] = *(const uint32_t*)(pAh + (ra)     * 80 + co);
                ah[mi][1] = *(const uint32_t*)(pAh + (ra + 8) * 80 + co);
                ah[mi][2] = *(const uint32_t*)(pAh + (ra)     * 80 + co + 16);
                ah[mi][3] = *(const uint32_t*)(pAh + (ra + 8) * 80 + co + 16);
                al[mi][0] = *(const uint32_t*)(pAl + (ra)     * 80 + co);
                al[mi][1] = *(const uint32_t*)(pAl + (ra + 8) * 80 + co);
                al[mi][2] = *(const uint32_t*)(pAl + (ra)     * 80 + co + 16);
                al[mi][3] = *(const uint32_t*)(pAl + (ra + 8) * 80 + co + 16);
            }
#pragma unroll
            for (int ni = 0; ni < 8; ni++) {
                int rb = wn * 64 + ni * 8 + g;
                int co = (kb + t * 2) * 2;
                uint32_t bh[2], bl[2];
                bh[0] = *(const uint32_t*)(pBh + rb * 80 + co);
                bh[1] = *(const uint32_t*)(pBh + rb * 80 + co + 16);
                bl[0] = *(const uint32_t*)(pBl + rb * 80 + co);
                bl[1] = *(const uint32_t*)(pBl + rb * 80 + co + 16);
#pragma unroll
                for (int mi = 0; mi < 2; mi++) {
                    mma16816(acc[mi][ni], ah[mi], bh);
                    mma16816(acc[mi][ni], al[mi], bh);
                    mma16816(acc[mi][ni], ah[mi], bl);
                }
            }
        }
        __syncthreads();
    }

#pragma unroll
    for (int mi = 0; mi < 2; mi++) {
        int m = m0 + wm * 32 + mi * 16 + g;
#pragma unroll
        for (int ni = 0; ni < 8; ni++) {
            int n = n0 + wn * 64 + ni * 8 + t * 2;
            float bx = __ldg(bias + n), by = __ldg(bias + n + 1);
            float2 v0 = {acc[mi][ni][0] + bx, acc[mi][ni][1] + by};
            float2 v1 = {acc[mi][ni][2] + bx, acc[mi][ni][3] + by};
            *(float2*)(zx + (size_t)m * kG + n) = v0;
            *(float2*)(zx + (size_t)(m + 8) * kG + n) = v1;
        }
    }
}

// ------------------------------ persistent HMMA scan (R12 structure) --------
// 128 CTAs: CTA = dir*64 + g owns 8 units (32 gate cols).
// Per step: z[64,32] = h[64,512] @ UrSlice[512,32], bf16 hi/lo 3-pass on HMMA.
#define SA_STRIDE 1040
#define OFF_AL 66560
#define OFF_BH 133120
#define OFF_BL 166400
#define OFF_ZX 199680
#define SCAN_SMEM 208128

__global__ __launch_bounds__(256, 1) void scan_kernel(
    const float* __restrict__ Ur_f, const float* __restrict__ Ur_b,
    const int* __restrict__ enc,
    float* __restrict__ out2, float* __restrict__ h_final,
    float* __restrict__ c_final, int layer2) {
    extern __shared__ char dynsmem[];
    char* pAh = dynsmem;
    char* pAl = dynsmem + OFF_AL;
    char* pBh = dynsmem + OFF_BH;
    char* pBl = dynsmem + OFF_BL;
    float* zex = (float*)(dynsmem + OFF_ZX);

    const int cta = blockIdx.x;
    const int d = cta >> 6;
    const int g = cta & 63;
    const int j0 = g * 8;
    const int tid = threadIdx.x;
    const int w = tid >> 5, lane = tid & 31;
    const int fg = lane >> 2, ft = lane & 3;
    const int m0 = (w & 3) * 16;
    const int n0 = (w >> 2) * 16;
    const int er = tid >> 2;
    const int eu = tid & 3;

    const float* __restrict__ Ur = d ? Ur_b : Ur_f;
    const float* __restrict__ ew = d ? g_embw1 : g_embw0;
    const float* __restrict__ zx = d ? g_zx1 : g_zx0;
    unsigned int* barp = &g_bar[layer2 * 2 + d];

    // fill B tiles: Bh/Bl[n][k], n = q*8+jj <-> Ur col q*512 + j0 + jj
    for (int i = tid; i < 16384; i += 256) {
        int n = i >> 9, k = i & 511;
        int q = n >> 3, jj = n & 7;
        float v = __ldg(Ur + (size_t)k * kG + q * kU + j0 + jj);
        __nv_bfloat16 hi = __float2bfloat16(v);
        float lo = v - __bfloat162float(hi);
        *(__nv_bfloat16*)(pBh + n * SA_STRIDE + k * 2) = hi;
        *(__nv_bfloat16*)(pBl + n * SA_STRIDE + k * 2) = __float2bfloat16(lo);
    }
    __syncthreads();

    float hp0 = 0.0f, hp1 = 0.0f, cp0 = 0.0f, cp1 = 0.0f;

    for (int s = 0; s < kT; ++s) {
        const int t = d ? (kT - 1 - s) : s;
        const int par = s & 1;
        const uint32_t* __restrict__ hin = g_hc[layer2][d][par];
        uint32_t* __restrict__ hout = g_hc[layer2][d][par ^ 1];

        const int tok = __ldg(enc + er * kT + t);
        const int msk = tok != 0;
        float zr[2][4];
        if (!layer2) {
#pragma unroll
            for (int q = 0; q < 4; q++) {
                zr[0][q] = __ldg(ew + (size_t)tok * kG + q * kU + j0 + eu);
                zr[1][q] = __ldg(ew + (size_t)tok * kG + q * kU + j0 + eu + 4);
            }
        } else {
            const float* zb = zx + ((size_t)t * kB + er) * kG;
#pragma unroll
            for (int q = 0; q < 4; q++) {
                zr[0][q] = __ldg(zb + q * kU + j0 + eu);
                zr[1][q] = __ldg(zb + q * kU + j0 + eu + 4);
            }
        }

        // stage h (packed hi|lo u32 [64][512]) -> Ah/Al bf16 smem tiles
        for (int i = tid; i < 8192; i += 256) {
            int r = i >> 7, c = i & 127;
            uint4 v = __ldcg((const uint4*)(hin + r * kU + c * 4));
            uint32_t hi01 = __byte_perm(v.x, v.y, 0x5410);
            uint32_t hi23 = __byte_perm(v.z, v.w, 0x5410);
            uint32_t lo01 = __byte_perm(v.x, v.y, 0x7632);
            uint32_t lo23 = __byte_perm(v.z, v.w, 0x7632);
            *(uint2*)(pAh + r * SA_STRIDE + c * 8) = make_uint2(hi01, hi23);
            *(uint2*)(pAl + r * SA_STRIDE + c * 8) = make_uint2(lo01, lo23);
        }
        __syncthreads();

        // HMMA: z[64,32], 3-pass hi/lo (Ah*Bh + Al*Bh + Ah*Bl)
        float acc[2][4] = {{0.f, 0.f, 0.f, 0.f}, {0.f, 0.f, 0.f, 0.f}};
#pragma unroll 4
        for (int kb = 0; kb < 512; kb += 16) {
            const int co = (kb + ft * 2) * 2;
            uint32_t ah[4], al[4];
            ah[0] = *(const uint32_t*)(pAh + (m0 + fg)     * SA_STRIDE + co);
            ah[1] = *(const uint32_t*)(pAh + (m0 + fg + 8) * SA_STRIDE + co);
            ah[2] = *(const uint32_t*)(pAh + (m0 + fg)     * SA_STRIDE + co + 16);
            ah[3] = *(const uint32_t*)(pAh + (m0 + fg + 8) * SA_STRIDE + co + 16);
            al[0] = *(const uint32_t*)(pAl + (m0 + fg)     * SA_STRIDE + co);
            al[1] = *(const uint32_t*)(pAl + (m0 + fg + 8) * SA_STRIDE + co);
            al[2] = *(const uint32_t*)(pAl + (m0 + fg)     * SA_STRIDE + co + 16);
            al[3] = *(const uint32_t*)(pAl + (m0 + fg + 8) * SA_STRIDE + co + 16);
#pragma unroll
            for (int ni = 0; ni < 2; ni++) {
                int rb = n0 + ni * 8 + fg;
                uint32_t bh[2], bl[2];
                bh[0] = *(const uint32_t*)(pBh + rb * SA_STRIDE + co);
                bh[1] = *(const uint32_t*)(pBh + rb * SA_STRIDE + co + 16);
                bl[0] = *(const uint32_t*)(pBl + rb * SA_STRIDE + co);
                bl[1] = *(const uint32_t*)(pBl + rb * SA_STRIDE + co + 16);
                mma16816(acc[ni], ah, bh);
                mma16816(acc[ni], al, bh);
                mma16816(acc[ni], ah, bl);
            }
        }
        // write z to exchange buffer
#pragma unroll
        for (int ni = 0; ni < 2; ni++) {
            int nc = n0 + ni * 8 + ft * 2;
            zex[(m0 + fg)     * 33 + nc]     = acc[ni][0];
            zex[(m0 + fg)     * 33 + nc + 1] = acc[ni][1];
            zex[(m0 + fg + 8) * 33 + nc]     = acc[ni][2];
            zex[(m0 + fg + 8) * 33 + nc + 1] = acc[ni][3];
        }
        __syncthreads();

        // LSTM epilogue: thread owns (er, eu) and (er, eu+4)
        float hn_s[2], cn_s[2];
        __nv_bfloat16 bhi_s[2], blo_s[2];
#pragma unroll
        for (int uu = 0; uu < 2; ++uu) {
            const int u = eu + uu * 4;
            float zi = zex[er * 33 +      u] + zr[uu][0];
            float zf = zex[er * 33 +  8 + u] + zr[uu][1];
            float zg = zex[er * 33 + 16 + u] + zr[uu][2];
            float zo = zex[er * 33 + 24 + u] + zr[uu][3];
            float ii = sigmoidf_(zi), ff = sigmoidf_(zf);
            float gg = tanhf(zg), oo = sigmoidf_(zo);
            float& hp = uu ? hp1 : hp0;
            float& cp = uu ? cp1 : cp0;
            float cn = ff * cp + ii * gg;
            float hn = oo * tanhf(cn);
            if (!msk) { hn = hp; cn = cp; }
            hp = hn; cp = cn;
            hn_s[uu] = hn; cn_s[uu] = cn;
            __nv_bfloat16 bhi = __float2bfloat16(hn);
            __nv_bfloat16 blo = __float2bfloat16(hn - __bfloat162float(bhi));
            bhi_s[uu] = bhi; blo_s[uu] = blo;
            unsigned short uh = *reinterpret_cast<unsigned short*>(&bhi);
            unsigned short ul = *reinterpret_cast<unsigned short*>(&blo);
            __stcg(&hout[er * kU + j0 + u], (uint32_t)uh | ((uint32_t)ul << 16));
        }

        // ----- R14-style barrier: arrive, deferred stores, spin-acquire -----
        if (s != kT - 1) {
            __syncthreads();                  // all h stores done (HB chain)
            if (tid == 0) bar_arrive_release(barp);
            // deferred output stores overlap barrier propagation
#pragma unroll
            for (int uu = 0; uu < 2; ++uu) {
                const int u = eu + uu * 4;
                if (!layer2) {
                    size_t idx = ((size_t)t * kB + er) * kF + d * kU + j0 + u;
                    g_ah[idx] = bhi_s[uu];
                    g_al[idx] = blo_s[uu];
                } else {
                    out2[((size_t)er * kT + t) * kF + d * kU + j0 + u] = hn_s[uu];
                }
            }
            if (tid == 0) {
                unsigned tgt = 64u * (unsigned)(s + 1);
                while (bar_poll_acquire(barp) < tgt) { }
            }
            __syncthreads();
        } else {
#pragma unroll
            for (int uu = 0; uu < 2; ++uu) {
                const int u = eu + uu * 4;
                if (!layer2) {
                    size_t idx = ((size_t)t * kB + er) * kF + d * kU + j0 + u;
                    g_ah[idx] = bhi_s[uu];
                    g_al[idx] = blo_s[uu];
                } else {
                    out2[((size_t)er * kT + t) * kF + d * kU + j0 + u] = hn_s[uu];
                    h_final[er * kF + d * kU + j0 + u] = hn_s[uu];
                    c_final[er * kF + d * kU + j0 + u] = cn_s[uu];
                }
            }
        }
    }
}

// ------------------------------ launch --------------------------------------
extern "C" void kernel_launch(void* const* d_in, const int* in_sizes, int n_in,
                              void* d_out, int out_size) {
    const int*   enc = (const int*)d_in[0];
    const float* emb = (const float*)d_in[1];
    const float* W1f = (const float*)d_in[2];
    const float* U1f = (const float*)d_in[3];
    const float* b1f = (const float*)d_in[4];
    const float* W1b = (const float*)d_in[5];
    const float* U1b = (const float*)d_in[6];
    const float* b1b = (const float*)d_in[7];
    const float* W2f = (const float*)d_in[8];
    const float* U2f = (const float*)d_in[9];
    const float* b2f = (const float*)d_in[10];
    const float* W2b = (const float*)d_in[11];
    const float* U2b = (const float*)d_in[12];
    const float* b2b = (const float*)d_in[13];

    float* out  = (float*)d_out;
    float* out2 = out;                                   // [B,T,2U]
    float* h2   = out + (size_t)kB * kT * kF;
    float* c2   = h2 + (size_t)kB * kF;

    cudaFuncSetAttribute(scan_kernel, cudaFuncAttributeMaxDynamicSharedMemorySize,
                         SCAN_SMEM);
    cudaFuncSetAttribute(mma_gemm_kernel, cudaFuncAttributeMaxDynamicSharedMemorySize,
                         MM_SMEM);

    // embW = emb @ W1 + b1  (fused f/b, BM=32: 128 CTAs)
    gemm_f32<<<dim3(16, 4, 2), 256>>>(emb, W1f, b1f, W1b, b1b);

    // W2 transpose + bf16 hi/lo split
    wsplit_kernel<<<dim3(64, 32, 2), 256>>>(W2f, W2b);

    // zero h buffers (both layers) + barrier counters, once
    init_kernel<<<128, 256>>>();

    // layer-1 scan (HMMA recurrent GEMM; emits bf16 hi/lo A operand)
    scan_kernel<<<128, 256, SCAN_SMEM>>>(U1f, U1b, enc,
                                         nullptr, nullptr, nullptr, 0);

    // layer-2 input projection: warp-mma bf16, 3-pass split, cp.async pipeline
    mma_gemm_kernel<<<dim3(16, 128, 2), 256, MM_SMEM>>>(b2f, b2b);

    // layer-2 scan -> outputs
    scan_kernel<<<128, 256, SCAN_SMEM>>>(U2f, U2b, enc,
                                         out2, h2, c2, 1);
}

// round 17
// speedup vs baseline: 1.1818x; 1.0028x over previous
#include <cuda_runtime.h>
#include <cuda_bf16.h>
#include <cstdint>

// ---------------------------------------------------------------------------
// StackedBidirectionalLSTMEncoder  (B=64, T=256, V=128, E=512, U=512)
// Round 17: R16 + unit-major B layout in the scan (n = jj*4 + q), so lane
// pairs hold all 4 gates of their cells -> one shfl_xor replaces the zex
// smem exchange + one syncthreads per step. z bitwise identical to R16.
// ---------------------------------------------------------------------------

#define kB 64
#define kT 256
#define kE 512
#define kU 512
#define kG 2048   /* 4U */
#define kF 1024   /* 2U */

// ------------------------------ scratch ------------------------------------
__device__ float g_zx0[33554432];                   // [t*B+b][2048] fwd (layer2)
__device__ float g_zx1[33554432];                   // bwd
__device__ __nv_bfloat16 g_ah[16777216];            // A hi  [16384][1024]
__device__ __nv_bfloat16 g_al[16777216];            // A lo
__device__ __nv_bfloat16 g_bh0[2097152];            // W2f^T hi [2048][1024]
__device__ __nv_bfloat16 g_bl0[2097152];
__device__ __nv_bfloat16 g_bh1[2097152];            // W2b^T hi
__device__ __nv_bfloat16 g_bl1[2097152];
__device__ float g_embw0[262144];                   // emb@W1f+b1f [128][2048]
__device__ float g_embw1[262144];
__device__ uint32_t g_hc[2][2][2][kB * kU];         // [layer][dir][par] hi|lo<<16
__device__ unsigned int g_bar[4];                   // [layer*2+dir]

// ------------------------------ f32x2 helpers ------------------------------
__device__ __forceinline__ unsigned long long pk2(float lo, float hi) {
    unsigned long long r;
    asm("mov.b64 %0, {%1, %2};" : "=l"(r) : "f"(lo), "f"(hi));
    return r;
}
__device__ __forceinline__ void upk2(unsigned long long v, float& lo, float& hi) {
    asm("mov.b64 {%0, %1}, %2;" : "=f"(lo), "=f"(hi) : "l"(v));
}
__device__ __forceinline__ unsigned long long ffma2(unsigned long long a,
                                                    unsigned long long b,
                                                    unsigned long long c) {
    unsigned long long d;
    asm("fma.rn.f32x2 %0, %1, %2, %3;" : "=l"(d) : "l"(a), "l"(b), "l"(c));
    return d;
}
__device__ __forceinline__ float sigmoidf_(float x) {
    return 1.0f / (1.0f + __expf(-x));
}

// ------------------------------ cp.async helpers ----------------------------
__device__ __forceinline__ uint32_t smem_u32(const void* p) {
    uint32_t a;
    asm("{ .reg .u64 t; cvta.to.shared.u64 t, %1; cvt.u32.u64 %0, t; }"
        : "=r"(a) : "l"(p));
    return a;
}
__device__ __forceinline__ void cp16(uint32_t d, const void* s) {
    asm volatile("cp.async.cg.shared.global [%0], [%1], 16;" :: "r"(d), "l"(s));
}
__device__ __forceinline__ void cp_commit() { asm volatile("cp.async.commit_group;" ::: "memory"); }
__device__ __forceinline__ void cp_wait1()  { asm volatile("cp.async.wait_group 1;" ::: "memory"); }
__device__ __forceinline__ void cp_wait0()  { asm volatile("cp.async.wait_group 0;" ::: "memory"); }

// release/acquire barrier primitives (gpu scope)
__device__ __forceinline__ void bar_arrive_release(unsigned int* p) {
    asm volatile("red.release.gpu.global.add.u32 [%0], %1;"
                 :: "l"(p), "r"(1u) : "memory");
}
__device__ __forceinline__ unsigned int bar_poll_acquire(unsigned int* p) {
    unsigned int v;
    asm volatile("ld.acquire.gpu.global.u32 %0, [%1];"
                 : "=r"(v) : "l"(p) : "memory");
    return v;
}

// bf16 warp mma: D(16x8,f32) += A(16x16 row) * B(16x8 col)
__device__ __forceinline__ void mma16816(float* c, const uint32_t* a,
                                         const uint32_t* b) {
    asm volatile(
        "mma.sync.aligned.m16n8k16.row.col.f32.bf16.bf16.f32 "
        "{%0,%1,%2,%3}, {%4,%5,%6,%7}, {%8,%9}, {%0,%1,%2,%3};"
        : "+f"(c[0]), "+f"(c[1]), "+f"(c[2]), "+f"(c[3])
        : "r"(a[0]), "r"(a[1]), "r"(a[2]), "r"(a[3]), "r"(b[0]), "r"(b[1]));
}

// ------------------------------ init ----------------------------------------
__global__ void init_kernel() {
    int i = blockIdx.x * blockDim.x + threadIdx.x;
    if (i < 4) g_bar[i] = 0u;
    uint32_t* h = (uint32_t*)g_hc;
    for (int j = i; j < 2 * 2 * 2 * kB * kU; j += gridDim.x * blockDim.x) h[j] = 0u;
}

// ------------------------------ fp32 GEMM (embW; BM=32, fused f/b) ---------
__global__ __launch_bounds__(256, 2) void gemm_f32(
    const float* __restrict__ A,
    const float* __restrict__ Wf, const float* __restrict__ biasf,
    const float* __restrict__ Wb, const float* __restrict__ biasb) {
    const int zsel = blockIdx.z;
    const float* __restrict__ W = zsel ? Wb : Wf;
    const float* __restrict__ bias = zsel ? biasb : biasf;
    float* __restrict__ C = zsel ? g_embw1 : g_embw0;
    __shared__ float As[16][36];
    __shared__ float Bs[16][128];
    const int tid = threadIdx.x;
    const int tx = tid & 31;
    const int ty = tid >> 5;
    const int m0 = blockIdx.y * 32;
    const int n0 = blockIdx.x * 128;

    unsigned long long acc[4][2];
#pragma unroll
    for (int i = 0; i < 4; i++) { acc[i][0] = pk2(0.f, 0.f); acc[i][1] = pk2(0.f, 0.f); }

    for (int k0 = 0; k0 < kE; k0 += 16) {
        if (tid < 128) {
            int m = tid >> 2, kc = (tid & 3) * 4;
            float4 v = *(const float4*)(A + (size_t)(m0 + m) * kE + k0 + kc);
            As[kc + 0][m] = v.x; As[kc + 1][m] = v.y;
            As[kc + 2][m] = v.z; As[kc + 3][m] = v.w;
        }
#pragma unroll
        for (int l = 0; l < 2; ++l) {
            int f = tid + l * 256;
            int kr = f >> 5, nc = (f & 31) * 4;
            *(float4*)&Bs[kr][nc] =
                *(const float4*)(W + (size_t)(k0 + kr) * kG + n0 + nc);
        }
        __syncthreads();
#pragma unroll
        for (int k = 0; k < 16; ++k) {
            float4 a = *(const float4*)&As[k][ty * 4];
            float4 b = *(const float4*)&Bs[k][tx * 4];
            unsigned long long bp0 = pk2(b.x, b.y), bp1 = pk2(b.z, b.w);
            float av[4] = {a.x, a.y, a.z, a.w};
#pragma unroll
            for (int i = 0; i < 4; ++i) {
                unsigned long long ad = pk2(av[i], av[i]);
                acc[i][0] = ffma2(ad, bp0, acc[i][0]);
                acc[i][1] = ffma2(ad, bp1, acc[i][1]);
            }
        }
        __syncthreads();
    }
#pragma unroll
    for (int i = 0; i < 4; ++i) {
        int m = m0 + ty * 4 + i;
        int n = n0 + tx * 4;
        float l0, h0, l1, h1;
        upk2(acc[i][0], l0, h0);
        upk2(acc[i][1], l1, h1);
        float4 v;
        v.x = l0 + bias[n + 0];
        v.y = h0 + bias[n + 1];
        v.z = l1 + bias[n + 2];
        v.w = h1 + bias[n + 3];
        *(float4*)(C + (size_t)m * kG + n) = v;
    }
}

// ------------------------------ W2 transpose + bf16 split -------------------
__global__ void wsplit_kernel(const float* __restrict__ W2f,
                              const float* __restrict__ W2b) {
    __shared__ float s[32][33];
    const int d = blockIdx.z;
    const float* __restrict__ W = d ? W2b : W2f;
    __nv_bfloat16* __restrict__ Bh = d ? g_bh1 : g_bh0;
    __nv_bfloat16* __restrict__ Bl = d ? g_bl1 : g_bl0;
    const int n0 = blockIdx.x * 32, k0 = blockIdx.y * 32;
    const int tx = threadIdx.x & 31, ty = threadIdx.x >> 5;
#pragma unroll
    for (int i = 0; i < 4; ++i) {
        int k = ty + i * 8;
        s[k][tx] = W[(size_t)(k0 + k) * kG + n0 + tx];
    }
    __syncthreads();
#pragma unroll
    for (int i = 0; i < 4; ++i) {
        int r = ty + i * 8;
        float v = s[tx][r];
        __nv_bfloat16 hi = __float2bfloat16(v);
        float lo = v - __bfloat162float(hi);
        size_t o = (size_t)(n0 + r) * 1024 + k0 + tx;
        Bh[o] = hi;
        Bl[o] = __float2bfloat16(lo);
    }
}

// ------------------------------ warp-mma layer-2 GEMM (validated 3-stage) ---
#define TILE_B   10240
#define STAGE_B  (4 * TILE_B)
#define MM_SMEM  (3 * STAGE_B)

__global__ __launch_bounds__(256, 1) void mma_gemm_kernel(
    const float* __restrict__ bias_f, const float* __restrict__ bias_b) {
    extern __shared__ char dynsmem[];
    const int tid = threadIdx.x;
    const int wid = tid >> 5, lane = tid & 31;
    const int g = lane >> 2, t = lane & 3;
    const int wm = wid & 3, wn = wid >> 2;
    const int d = blockIdx.z;
    const int n0 = blockIdx.x * 128;
    const int m0 = blockIdx.y * 128;
    const __nv_bfloat16* __restrict__ Bh = d ? g_bh1 : g_bh0;
    const __nv_bfloat16* __restrict__ Bl = d ? g_bl1 : g_bl0;
    const float* __restrict__ bias = d ? bias_b : bias_f;
    float* __restrict__ zx = d ? g_zx1 : g_zx0;

    const uint32_t sb32 = smem_u32(dynsmem);

    float acc[2][8][4];
#pragma unroll
    for (int mi = 0; mi < 2; mi++)
#pragma unroll
        for (int ni = 0; ni < 8; ni++)
#pragma unroll
            for (int v = 0; v < 4; v++) acc[mi][ni][v] = 0.0f;

    auto load_chunk = [&](int s, int kc) {
        const uint32_t base = sb32 + (uint32_t)s * STAGE_B;
        const int k0 = kc * 32;
        for (int idx = tid; idx < 2048; idx += 256) {
            int tile = idx >> 9;
            int r = (idx >> 2) & 127;
            int c = idx & 3;
            const __nv_bfloat16* src;
            if (tile < 2) src = (tile == 0 ? g_ah : g_al) + (size_t)(m0 + r) * 1024 + k0 + c * 8;
            else          src = (tile == 2 ? Bh : Bl)     + (size_t)(n0 + r) * 1024 + k0 + c * 8;
            cp16(base + tile * TILE_B + r * 80 + c * 16, src);
        }
        cp_commit();
    };

    load_chunk(0, 0);
    load_chunk(1, 1);

    for (int c = 0; c < 32; ++c) {
        if (c + 1 < 32) cp_wait1(); else cp_wait0();
        __syncthreads();
        if (c + 2 < 32) load_chunk((c + 2) % 3, c + 2);

        const char* stg = dynsmem + (size_t)(c % 3) * STAGE_B;
        const char* pAh = stg;
        const char* pAl = stg + TILE_B;
        const char* pBh = stg + 2 * TILE_B;
        const char* pBl = stg + 3 * TILE_B;

#pragma unroll
        for (int ks = 0; ks < 2; ++ks) {
            const int kb = ks * 16;
            uint32_t ah[2][4], al[2][4];
#pragma unroll
            for (int mi = 0; mi < 2; mi++) {
                int ra = wm * 32 + mi * 16 + g;
                int co = (kb + t * 2) * 2;
                ah[mi][0] = *(const uint32_t*)(pAh + (ra)     * 80 + co);
                ah[mi][1] = *(const uint32_t*)(pAh + (ra + 8) * 80 + co);
                ah[mi][2] = *(const uint32_t*)(pAh + (ra)     * 80 + co + 16);
                ah[mi][3] = *(const uint32_t*)(pAh + (ra + 8) * 80 + co + 16);
                al[mi][0] = *(const uint32_t*)(pAl + (ra)     * 80 + co);
                al[mi][1] = *(const uint32_t*)(pAl + (ra + 8) * 80 + co);
                al[mi][2] = *(const uint32_t*)(pAl + (ra)     * 80 + co + 16);
                al[mi][3] = *(const uint32_t*)(pAl + (ra + 8) * 80 + co + 16);
            }
#pragma unroll
            for (int ni = 0; ni < 8; ni++) {
                int rb = wn * 64 + ni * 8 + g;
                int co = (kb + t * 2) * 2;
                uint32_t bh[2], bl[2];
                bh[0] = *(const uint32_t*)(pBh + rb * 80 + co);
                bh[1] = *(const uint32_t*)(pBh + rb * 80 + co + 16);
                bl[0] = *(const uint32_t*)(pBl + rb * 80 + co);
                bl[1] = *(const uint32_t*)(pBl + rb * 80 + co + 16);
#pragma unroll
                for (int mi = 0; mi < 2; mi++) {
                    mma16816(acc[mi][ni], ah[mi], bh);
                    mma16816(acc[mi][ni], al[mi], bh);
                    mma16816(acc[mi][ni], ah[mi], bl);
                }
            }
        }
        __syncthreads();
    }

#pragma unroll
    for (int mi = 0; mi < 2; mi++) {
        int m = m0 + wm * 32 + mi * 16 + g;
#pragma unroll
        for (int ni = 0; ni < 8; ni++) {
            int n = n0 + wn * 64 + ni * 8 + t * 2;
            float bx = __ldg(bias + n), by = __ldg(bias + n + 1);
            float2 v0 = {acc[mi][ni][0] + bx, acc[mi][ni][1] + by};
            float2 v1 = {acc[mi][ni][2] + bx, acc[mi][ni][3] + by};
            *(float2*)(zx + (size_t)m * kG + n) = v0;
            *(float2*)(zx + (size_t)(m + 8) * kG + n) = v1;
        }
    }
}

// ------------------------------ persistent HMMA scan ------------------------
// 128 CTAs: CTA = dir*64 + g owns 8 units (32 gate cols, UNIT-MAJOR n=jj*4+q).
// Lane pairs (ft, ft^1) hold all 4 gates of their cells -> shfl epilogue.
#define SA_STRIDE 1040
#define OFF_AL 66560
#define OFF_BH 133120
#define OFF_BL 166400
#define SCAN_SMEM 199680

__global__ __launch_bounds__(256, 1) void scan_kernel(
    const float* __restrict__ Ur_f, const float* __restrict__ Ur_b,
    const int* __restrict__ enc,
    float* __restrict__ out2, float* __restrict__ h_final,
    float* __restrict__ c_final, int layer2) {
    extern __shared__ char dynsmem[];
    char* pAh = dynsmem;
    char* pAl = dynsmem + OFF_AL;
    char* pBh = dynsmem + OFF_BH;
    char* pBl = dynsmem + OFF_BL;

    const int cta = blockIdx.x;
    const int d = cta >> 6;
    const int g = cta & 63;
    const int j0 = g * 8;
    const int tid = threadIdx.x;
    const int w = tid >> 5, lane = tid & 31;
    const int fg = lane >> 2, ft = lane & 3;
    const int m0 = (w & 3) * 16;
    const int n0 = (w >> 2) * 16;
    const int odd = ft & 1;
    // owned cells: row b, units u[ni] = (w>>2)*4 + ni*2 + (ft>>1)
    const int b = m0 + fg + odd * 8;
    const int ub = (w >> 2) * 4 + (ft >> 1);

    const float* __restrict__ Ur = d ? Ur_b : Ur_f;
    const float* __restrict__ ew = d ? g_embw1 : g_embw0;
    const float* __restrict__ zx = d ? g_zx1 : g_zx0;
    unsigned int* barp = &g_bar[layer2 * 2 + d];

    // fill B tiles UNIT-MAJOR: smem row n = jj*4 + q <-> Ur col q*512 + j0 + jj
    for (int i = tid; i < 16384; i += 256) {
        int n = i >> 9, k = i & 511;
        int q = n & 3, jj = n >> 2;
        float v = __ldg(Ur + (size_t)k * kG + q * kU + j0 + jj);
        __nv_bfloat16 hi = __float2bfloat16(v);
        float lo = v - __bfloat162float(hi);
        *(__nv_bfloat16*)(pBh + n * SA_STRIDE + k * 2) = hi;
        *(__nv_bfloat16*)(pBl + n * SA_STRIDE + k * 2) = __float2bfloat16(lo);
    }
    __syncthreads();

    float hp[2] = {0.f, 0.f}, cp[2] = {0.f, 0.f};

    for (int s = 0; s < kT; ++s) {
        const int t = d ? (kT - 1 - s) : s;
        const int par = s & 1;
        const uint32_t* __restrict__ hin = g_hc[layer2][d][par];
        uint32_t* __restrict__ hout = g_hc[layer2][d][par ^ 1];

        const int tok = __ldg(enc + b * kT + t);
        const int msk = tok != 0;
        float zr[2][4];
        if (!layer2) {
#pragma unroll
            for (int ni = 0; ni < 2; ++ni)
#pragma unroll
                for (int q = 0; q < 4; q++)
                    zr[ni][q] = __ldg(ew + (size_t)tok * kG + q * kU + j0 + ub + ni * 2);
        } else {
            const float* zb = zx + ((size_t)t * kB + b) * kG;
#pragma unroll
            for (int ni = 0; ni < 2; ++ni)
#pragma unroll
                for (int q = 0; q < 4; q++)
                    zr[ni][q] = __ldg(zb + q * kU + j0 + ub + ni * 2);
        }

        // stage h (packed hi|lo u32 [64][512]) -> Ah/Al bf16 smem tiles
        for (int i = tid; i < 8192; i += 256) {
            int r = i >> 7, c = i & 127;
            uint4 v = __ldcg((const uint4*)(hin + r * kU + c * 4));
            uint32_t hi01 = __byte_perm(v.x, v.y, 0x5410);
            uint32_t hi23 = __byte_perm(v.z, v.w, 0x5410);
            uint32_t lo01 = __byte_perm(v.x, v.y, 0x7632);
            uint32_t lo23 = __byte_perm(v.z, v.w, 0x7632);
            *(uint2*)(pAh + r * SA_STRIDE + c * 8) = make_uint2(hi01, hi23);
            *(uint2*)(pAl + r * SA_STRIDE + c * 8) = make_uint2(lo01, lo23);
        }
        __syncthreads();

        // HMMA: z[64,32], 3-pass hi/lo (Ah*Bh + Al*Bh + Ah*Bl)
        float acc[2][4] = {{0.f, 0.f, 0.f, 0.f}, {0.f, 0.f, 0.f, 0.f}};
#pragma unroll 4
        for (int kb = 0; kb < 512; kb += 16) {
            const int co = (kb + ft * 2) * 2;
            uint32_t ah[4], al[4];
            ah[0] = *(const uint32_t*)(pAh + (m0 + fg)     * SA_STRIDE + co);
            ah[1] = *(const uint32_t*)(pAh + (m0 + fg + 8) * SA_STRIDE + co);
            ah[2] = *(const uint32_t*)(pAh + (m0 + fg)     * SA_STRIDE + co + 16);
            ah[3] = *(const uint32_t*)(pAh + (m0 + fg + 8) * SA_STRIDE + co + 16);
            al[0] = *(const uint32_t*)(pAl + (m0 + fg)     * SA_STRIDE + co);
            al[1] = *(const uint32_t*)(pAl + (m0 + fg + 8) * SA_STRIDE + co);
            al[2] = *(const uint32_t*)(pAl + (m0 + fg)     * SA_STRIDE + co + 16);
            al[3] = *(const uint32_t*)(pAl + (m0 + fg + 8) * SA_STRIDE + co + 16);
#pragma unroll
            for (int ni = 0; ni < 2; ni++) {
                int rb = n0 + ni * 8 + fg;
                uint32_t bh[2], bl[2];
                bh[0] = *(const uint32_t*)(pBh + rb * SA_STRIDE + co);
                bh[1] = *(const uint32_t*)(pBh + rb * SA_STRIDE + co + 16);
                bl[0] = *(const uint32_t*)(pBl + rb * SA_STRIDE + co);
                bl[1] = *(const uint32_t*)(pBl + rb * SA_STRIDE + co + 16);
                mma16816(acc[ni], ah, bh);
                mma16816(acc[ni], al, bh);
                mma16816(acc[ni], ah, bl);
            }
        }

        // ---- shuffle epilogue: pair (ft, ft^1) exchanges gate halves --------
        // even lane: own acc[ni][0,1] = gates q0,q0+1 @ row fg; needs gates 2,3
        // odd lane : own acc[ni][2,3] = gates 2,3 @ row fg+8; needs gates 0,1
        float hn_s[2], cn_s[2];
        uint32_t hpk_s[2];
#pragma unroll
        for (int ni = 0; ni < 2; ++ni) {
            float s0 = odd ? acc[ni][0] : acc[ni][2];
            float s1 = odd ? acc[ni][1] : acc[ni][3];
            float r0 = __shfl_xor_sync(0xffffffffu, s0, 1);
            float r1 = __shfl_xor_sync(0xffffffffu, s1, 1);
            float g0 = odd ? acc[ni][2] : acc[ni][0];
            float g1 = odd ? acc[ni][3] : acc[ni][1];
            float zi = (odd ? r0 : g0) + zr[ni][0];
            float zf = (odd ? r1 : g1) + zr[ni][1];
            float zg = (odd ? g0 : r0) + zr[ni][2];
            float zo = (odd ? g1 : r1) + zr[ni][3];
            float ii = sigmoidf_(zi), ff = sigmoidf_(zf);
            float gg = tanhf(zg), oo = sigmoidf_(zo);
            float cn = ff * cp[ni] + ii * gg;
            float hn = oo * tanhf(cn);
            if (!msk) { hn = hp[ni]; cn = cp[ni]; }
            hp[ni] = hn; cp[ni] = cn;
            hn_s[ni] = hn; cn_s[ni] = cn;
            __nv_bfloat16 bhi = __float2bfloat16(hn);
            __nv_bfloat16 blo = __float2bfloat16(hn - __bfloat162float(bhi));
            unsigned short uh = *reinterpret_cast<unsigned short*>(&bhi);
            unsigned short ul = *reinterpret_cast<unsigned short*>(&blo);
            hpk_s[ni] = (uint32_t)uh | ((uint32_t)ul << 16);
            __stcg(&hout[b * kU + j0 + ub + ni * 2], hpk_s[ni]);
        }

        // ----- barrier: arrive, deferred output stores, spin-acquire --------
        if (s != kT - 1) {
            __syncthreads();                  // all h stores done (HB chain)
            if (tid == 0) bar_arrive_release(barp);
#pragma unroll
            for (int ni = 0; ni < 2; ++ni) {
                const int u = ub + ni * 2;
                if (!layer2) {
                    size_t idx = ((size_t)t * kB + b) * kF + d * kU + j0 + u;
                    g_ah[idx] = *reinterpret_cast<__nv_bfloat16*>(&hpk_s[ni]);
                    unsigned short ul = (unsigned short)(hpk_s[ni] >> 16);
                    g_al[idx] = *reinterpret_cast<__nv_bfloat16*>(&ul);
                } else {
                    out2[((size_t)b * kT + t) * kF + d * kU + j0 + u] = hn_s[ni];
                }
            }
            if (tid == 0) {
                unsigned tgt = 64u * (unsigned)(s + 1);
                while (bar_poll_acquire(barp) < tgt) { }
            }
            __syncthreads();
        } else {
#pragma unroll
            for (int ni = 0; ni < 2; ++ni) {
                const int u = ub + ni * 2;
                if (!layer2) {
                    size_t idx = ((size_t)t * kB + b) * kF + d * kU + j0 + u;
                    g_ah[idx] = *reinterpret_cast<__nv_bfloat16*>(&hpk_s[ni]);
                    unsigned short ul = (unsigned short)(hpk_s[ni] >> 16);
                    g_al[idx] = *reinterpret_cast<__nv_bfloat16*>(&ul);
                } else {
                    out2[((size_t)b * kT + t) * kF + d * kU + j0 + u] = hn_s[ni];
                    h_final[b * kF + d * kU + j0 + u] = hn_s[ni];
                    c_final[b * kF + d * kU + j0 + u] = cn_s[ni];
                }
            }
        }
    }
}

// ------------------------------ launch --------------------------------------
extern "C" void kernel_launch(void* const* d_in, const int* in_sizes, int n_in,
                              void* d_out, int out_size) {
    const int*   enc = (const int*)d_in[0];
    const float* emb = (const float*)d_in[1];
    const float* W1f = (const float*)d_in[2];
    const float* U1f = (const float*)d_in[3];
    const float* b1f = (const float*)d_in[4];
    const float* W1b = (const float*)d_in[5];
    const float* U1b = (const float*)d_in[6];
    const float* b1b = (const float*)d_in[7];
    const float* W2f = (const float*)d_in[8];
    const float* U2f = (const float*)d_in[9];
    const float* b2f = (const float*)d_in[10];
    const float* W2b = (const float*)d_in[11];
    const float* U2b = (const float*)d_in[12];
    const float* b2b = (const float*)d_in[13];

    float* out  = (float*)d_out;
    float* out2 = out;                                   // [B,T,2U]
    float* h2   = out + (size_t)kB * kT * kF;
    float* c2   = h2 + (size_t)kB * kF;

    cudaFuncSetAttribute(scan_kernel, cudaFuncAttributeMaxDynamicSharedMemorySize,
                         SCAN_SMEM);
    cudaFuncSetAttribute(mma_gemm_kernel, cudaFuncAttributeMaxDynamicSharedMemorySize,
                         MM_SMEM);

    // embW = emb @ W1 + b1  (fused f/b, BM=32: 128 CTAs)
    gemm_f32<<<dim3(16, 4, 2), 256>>>(emb, W1f, b1f, W1b, b1b);

    // W2 transpose + bf16 hi/lo split
    wsplit_kernel<<<dim3(64, 32, 2), 256>>>(W2f, W2b);

    // zero h buffers (both layers) + barrier counters, once
    init_kernel<<<128, 256>>>();

    // layer-1 scan (HMMA recurrent GEMM; emits bf16 hi/lo A operand)
    scan_kernel<<<128, 256, SCAN_SMEM>>>(U1f, U1b, enc,
                                         nullptr, nullptr, nullptr, 0);

    // layer-2 input projection: warp-mma bf16, 3-pass split, cp.async pipeline
    mma_gemm_kernel<<<dim3(16, 128, 2), 256, MM_SMEM>>>(b2f, b2b);

    // layer-2 scan -> outputs
    scan_kernel<<<128, 256, SCAN_SMEM>>>(U2f, U2b, enc,
                                         out2, h2, c2, 1);
}